// round 6
// baseline (speedup 1.0000x reference)
#include <cuda_runtime.h>
#include <stdint.h>

// Problem dims (fixed by the dataset)
#define NCLS   19
#define BATCH  2
#define SPATIAL (4*256*384)          // F*H*W = 393216
#define NPIX   (BATCH*SPATIAL)       // 786432
#define KB     8192                  // error buckets (uniform in [0,1])
#define KBF    8192.0f

// Count-only histogram: g_hist[class][bucket][fg], u32 counts (1.2 MB).
// Items in a bucket use the bucket midpoint as their error value:
// |loss error| <= 1/(2*KB) = 6.1e-5 worst-case (tolerance 1e-3).
// Zero-initialized statically; scan_kernel re-zeroes after reading so every
// graph replay starts from a clean histogram.
__device__ unsigned int g_hist[NCLS][KB][2];
__device__ double g_loss[NCLS];
__device__ int    g_present[NCLS];
__device__ int    g_is64;
__device__ unsigned int g_done;   // last-block ticket; reset by the last block

// Sniff target dtype. int64 labels in [0,19): every odd 32-bit word is 0
// (LE high half). int32 labels: odd words nonzero w.p. 18/19 each.
// 256 odd words all zero => int64 (false positive prob 19^-256 ~ 0).
__global__ void detect_kernel(const unsigned int* __restrict__ w) {
    unsigned int nz = 0;
    for (int k = threadIdx.x; k < 256; k += 32) nz |= w[2 * k + 1];
#pragma unroll
    for (int off = 16; off > 0; off >>= 1)
        nz |= __shfl_down_sync(0xffffffffu, nz, off);
    if (threadIdx.x == 0) g_is64 = (nz == 0u) ? 1 : 0;
}

// 4 pixels per thread. One RED.ADD.32 per (pixel,class) item.
__global__ void hist_kernel(const float* __restrict__ inp,
                            const void* __restrict__ tgt) {
    int q = blockIdx.x * blockDim.x + threadIdx.x;   // quad index
    if (q >= NPIX / 4) return;
    int n = q * 4;
    int b = (n >= SPATIAL) ? 1 : 0;
    int s = n - b * SPATIAL;

    int lab[4];
    if (g_is64) {
        longlong2 L0 = ((const longlong2*)tgt)[2 * q];
        longlong2 L1 = ((const longlong2*)tgt)[2 * q + 1];
        lab[0] = (int)L0.x; lab[1] = (int)L0.y;
        lab[2] = (int)L1.x; lab[3] = (int)L1.y;
    } else {
        int4 L = ((const int4*)tgt)[q];
        lab[0] = L.x; lab[1] = L.y; lab[2] = L.z; lab[3] = L.w;
    }

    const float* base = inp + (size_t)b * NCLS * SPATIAL + s;
#pragma unroll
    for (int c = 0; c < NCLS; ++c) {
        float4 p = *(const float4*)(base + (size_t)c * SPATIAL);
        float pv[4] = {p.x, p.y, p.z, p.w};
#pragma unroll
        for (int j = 0; j < 4; ++j) {
            int fg = (c == lab[j]) ? 1 : 0;
            float e = fg ? (1.0f - pv[j]) : pv[j];
            int bk = min((int)(__saturatef(e) * KBF), KB - 1);
            atomicAdd(&g_hist[c][bk][fg], 1u);   // result unused -> RED.32
        }
    }
}

// One block per class, 256 threads, CH=32 buckets/thread, DESCENDING order.
// Loads stashed in registers (uint4 = 2 buckets per LDG.128), slice re-zeroed
// for the next graph replay. Block scan of chunk totals gives exact exclusive
// prefixes. Per bucket (I = gts - cum_fg, U = gts + cum_nonfg, exact ints):
//   contribution = mid * (n1*U2 + I2*n0) / (U*U2),  I2 = I-n1, U2 = U+n0
// (telescoped jaccard; order within a bucket provably cancels). All terms >= 0
// so fp32 accumulation is well-conditioned. Empty buckets contribute 0.
// The last block to finish performs the cross-class mean and writes d_out.
__global__ void scan_kernel(float* __restrict__ out, int out_size) {
    const int c = blockIdx.x;
    const int t = threadIdx.x;
    const int CH = KB / 256;  // 32 buckets per thread

    __shared__ unsigned int s1[256], s0[256];
    __shared__ float sAcc[256];

    // Thread t owns buckets [cb, cb+CH): thread 0 gets the TOP buckets.
    const int cb = KB - (t + 1) * CH;
    unsigned int n1r[CH], n0r[CH];
    unsigned int n1c = 0, n0c = 0;
    {
        const uint4* p = reinterpret_cast<const uint4*>(&g_hist[c][cb][0]);
#pragma unroll
        for (int k = 0; k < CH / 2; ++k) {
            uint4 v = p[k];
            n0r[2 * k]     = v.x; n1r[2 * k]     = v.y;
            n0r[2 * k + 1] = v.z; n1r[2 * k + 1] = v.w;
            n0c += v.x + v.z;
            n1c += v.y + v.w;
        }
        // re-zero this slice for the next replay
        uint4 z = make_uint4(0u, 0u, 0u, 0u);
        uint4* pw = reinterpret_cast<uint4*>(&g_hist[c][cb][0]);
#pragma unroll
        for (int k = 0; k < CH / 2; ++k) pw[k] = z;
    }
    s1[t] = n1c; s0[t] = n0c;
    __syncthreads();

    // Inclusive Hillis-Steele scan over 256 chunk totals
    unsigned int x1 = n1c, x0 = n0c;
    for (int off = 1; off < 256; off <<= 1) {
        unsigned int y1 = 0, y0 = 0;
        if (t >= off) { y1 = s1[t - off]; y0 = s0[t - off]; }
        __syncthreads();
        x1 += y1; x0 += y0;
        s1[t] = x1; s0[t] = x0;
        __syncthreads();
    }
    const unsigned int gts_u = s1[255];

    float acc = 0.0f;
    if (gts_u > 0) {
        unsigned int I = gts_u - (x1 - n1c);   // gts - exclusive fg prefix
        unsigned int U = gts_u + (x0 - n0c);   // gts + exclusive nonfg prefix
#pragma unroll
        for (int i = CH - 1; i >= 0; --i) {    // descending within chunk
            unsigned int n1 = n1r[i], n0 = n0r[i];
            unsigned int I2 = I - n1;
            unsigned int U2 = U + n0;
            float mid = ((float)(cb + i) + 0.5f) * (1.0f / KBF);
            float num = (float)n1 * (float)U2 + (float)I2 * (float)n0;
            acc += mid * __fdividef(num, (float)U * (float)U2);
            I = I2; U = U2;
        }
    }

    sAcc[t] = acc;
    __syncthreads();
    for (int off = 128; off > 0; off >>= 1) {
        if (t < off) sAcc[t] += sAcc[t + off];
        __syncthreads();
    }

    if (t == 0) {
        g_loss[c] = (double)sAcc[0];
        g_present[c] = (gts_u > 0) ? 1 : 0;
        __threadfence();
        unsigned int ticket = atomicAdd(&g_done, 1u);
        if (ticket == NCLS - 1) {          // last class block: finalize
            __threadfence();
            double v = 0.0; int pr = 0;
            for (int k = 0; k < NCLS; ++k) {
                if (g_present[k]) { v += g_loss[k]; pr++; }
            }
            out[0] = (float)(v / (double)(pr > 0 ? pr : 1));
            for (int i = 1; i < out_size; ++i) out[i] = 0.0f;
            g_done = 0u;                   // reset for next replay
        }
    }
}

extern "C" void kernel_launch(void* const* d_in, const int* in_sizes, int n_in,
                              void* d_out, int out_size) {
    const float* inp = (const float*)d_in[0];
    const void*  tgt = d_in[1];

    detect_kernel<<<1, 32>>>((const unsigned int*)tgt);
    hist_kernel<<<(NPIX / 4 + 255) / 256, 256>>>(inp, tgt);
    scan_kernel<<<NCLS, 256>>>((float*)d_out, out_size);
}